// round 3
// baseline (speedup 1.0000x reference)
#include <cuda_runtime.h>
#include <cstdint>

typedef unsigned long long u64;

// ---------- f32x2 packed helpers (sm_103a FFMA2 path, PTX-only) ----------
__device__ __forceinline__ u64 pack2(float x, float y) {
    u64 r; asm("mov.b64 %0, {%1,%2};" : "=l"(r) : "f"(x), "f"(y)); return r;
}
__device__ __forceinline__ void unpack2(u64 v, float& x, float& y) {
    asm("mov.b64 {%0,%1}, %2;" : "=f"(x), "=f"(y) : "l"(v));
}
// fma2(acc, b, c) = b*c + acc   (accumulator-first convention)
__device__ __forceinline__ u64 fma2(u64 acc, u64 b, u64 c) {
    u64 d; asm("fma.rn.f32x2 %0, %1, %2, %3;" : "=l"(d) : "l"(b), "l"(c), "l"(acc)); return d;
}
__device__ __forceinline__ u64 add2(u64 a, u64 b) {
    u64 d; asm("add.rn.f32x2 %0, %1, %2;" : "=l"(d) : "l"(a), "l"(b)); return d;
}
__device__ __forceinline__ u64 relu2(u64 a) {
    float x, y; unpack2(a, x, y);
    return pack2(fmaxf(x, 0.f), fmaxf(y, 0.f));
}
__device__ __forceinline__ u64 dup(float w) { return pack2(w, w); }

// ---------- shared-memory weight cache (all weights duplicated as (w,w) pairs) ----------
struct Smem {
    u64 w2d[128 * 40];   // w2d[j*40+o] = dup(W2[o][j]), o<39, col 39 zero-padded
    u64 w3d[128 * 40];   // w3d[i*40+o] = dup(W3[i][o])
    u64 wmvd[128 * 16];  // wmvd[i*16+ii] = dup(Wm[ii][i]); +8: dup(Wv[ii][i])
    u64 wd1d[32 * 20];   // wd1d[h*20+t] = dup(Wd1[h][5+t])
    u64 wd2d[32 * 12];   // wd2d[h*12+o] = dup(Wd2[o][h])
    u64 b2d[40];
    u64 b3d[128];
    u64 bmd[8];
    u64 bvd[8];
    u64 bd1d[32];        // bd1 + Wd1[:,0]  (node-0 one-hot folded)
    u64 bd2d[12];
    float bias1[4 * 128]; // b1[j] + W1[j][0] + W1[j][6+e]  (edge one-hots folded)
    float w1s[128 * 4];   // W1[j][10+k], stride 4
};

#define NT 128

__global__ void __launch_bounds__(NT) vae_kernel(
    const float* __restrict__ initial_c,
    const float* __restrict__ current_c,
    const float* __restrict__ eps,
    const float* __restrict__ W1, const float* __restrict__ b1,
    const float* __restrict__ W2, const float* __restrict__ b2,
    const float* __restrict__ W3, const float* __restrict__ b3,
    const float* __restrict__ Wm, const float* __restrict__ bm,
    const float* __restrict__ Wv, const float* __restrict__ bv,
    const float* __restrict__ Wd1, const float* __restrict__ bd1,
    const float* __restrict__ Wd2, const float* __restrict__ bd2,
    float* __restrict__ out, int Bn)
{
    extern __shared__ unsigned char smem_raw[];
    Smem& s = *reinterpret_cast<Smem*>(smem_raw);
    const int tid = threadIdx.x;

    // ---------------- build weight cache ----------------
    for (int idx = tid; idx < 128 * 40; idx += NT) {
        int j = idx / 40, o = idx % 40;
        s.w2d[idx] = (o < 39) ? dup(W2[o * 128 + j]) : 0ull;
    }
    for (int idx = tid; idx < 128 * 40; idx += NT) {
        int i = idx / 40, o = idx % 40;
        s.w3d[idx] = (o < 39) ? dup(W3[i * 39 + o]) : 0ull;
    }
    for (int idx = tid; idx < 128 * 16; idx += NT) {
        int i = idx / 16, ii = idx % 16;
        s.wmvd[idx] = (ii < 8) ? dup(Wm[ii * 128 + i]) : dup(Wv[(ii - 8) * 128 + i]);
    }
    for (int idx = tid; idx < 32 * 20; idx += NT) {
        int h = idx / 20, t = idx % 20;
        s.wd1d[idx] = dup(Wd1[h * 25 + 5 + t]);
    }
    for (int idx = tid; idx < 32 * 12; idx += NT) {
        int h = idx / 12, o = idx % 12;
        s.wd2d[idx] = dup(Wd2[o * 32 + h]);
    }
    for (int idx = tid; idx < 40; idx += NT)
        s.b2d[idx] = (idx < 39) ? dup(b2[idx]) : 0ull;
    for (int idx = tid; idx < 128; idx += NT)
        s.b3d[idx] = dup(b3[idx]);
    if (tid < 8) { s.bmd[tid] = dup(bm[tid]); s.bvd[tid] = dup(bv[tid]); }
    for (int idx = tid; idx < 32; idx += NT)
        s.bd1d[idx] = dup(bd1[idx] + Wd1[idx * 25 + 0]);
    for (int idx = tid; idx < 12; idx += NT)
        s.bd2d[idx] = dup(bd2[idx]);
    for (int idx = tid; idx < 512; idx += NT) {
        int e = idx >> 7, j = idx & 127;
        s.bias1[idx] = b1[j] + W1[j * 13 + 0] + W1[j * 13 + 6 + e];
    }
    for (int idx = tid; idx < 512; idx += NT) {
        int j = idx >> 2, k = idx & 3;
        s.w1s[idx] = (k < 3) ? W1[j * 13 + 10 + k] : 0.f;
    }
    __syncthreads();

    // ---------------- per-thread: 2 rows ----------------
    const int t = blockIdx.x * NT + tid;
    const int r0 = 2 * t;
    if (r0 >= Bn) return;
    const int r1 = r0 + 1;

    const int PRED[4][3] = {{0,10,14},{1,11,18},{2,12,22},{3,13,26}};
    float px[4][3], py[4][3];
    #pragma unroll
    for (int e = 0; e < 4; e++)
        #pragma unroll
        for (int k = 0; k < 3; k++) {
            px[e][k] = current_c[(size_t)r0 * 30 + PRED[e][k]];
            py[e][k] = current_c[(size_t)r1 * 30 + PRED[e][k]];
        }

    // message passing: x39 = sum_e relu(W2 @ relu(W1p @ pred_e + bias1e) + b2)
    u64 sum39[39];
    #pragma unroll
    for (int c = 0; c < 3; c++) {
        const int ob = c * 13;
        #pragma unroll
        for (int e = 0; e < 4; e++) {
            u64 acc[13];
            #pragma unroll
            for (int oo = 0; oo < 13; oo++) acc[oo] = s.b2d[ob + oo];
            #pragma unroll 4
            for (int j = 0; j < 128; j++) {
                float hx = s.bias1[e * 128 + j], hy = hx;
                #pragma unroll
                for (int k = 0; k < 3; k++) {
                    float w = s.w1s[j * 4 + k];
                    hx = fmaf(w, px[e][k], hx);
                    hy = fmaf(w, py[e][k], hy);
                }
                hx = fmaxf(hx, 0.f); hy = fmaxf(hy, 0.f);
                u64 h2 = pack2(hx, hy);
                const u64* wr = s.w2d + j * 40 + ob;
                #pragma unroll
                for (int oo = 0; oo < 13; oo++) acc[oo] = fma2(acc[oo], wr[oo], h2);
            }
            #pragma unroll
            for (int oo = 0; oo < 13; oo++) {
                u64 r = relu2(acc[oo]);
                sum39[ob + oo] = (e == 0) ? r : add2(sum39[ob + oo], r);
            }
        }
    }

    // layer3 + means/log_var fused
    u64 macc[8], vacc[8];
    #pragma unroll
    for (int ii = 0; ii < 8; ii++) { macc[ii] = s.bmd[ii]; vacc[ii] = s.bvd[ii]; }
    #pragma unroll 2
    for (int i = 0; i < 128; i++) {
        u64 a = s.b3d[i];
        const u64* wr = s.w3d + i * 40;
        #pragma unroll
        for (int o = 0; o < 39; o++) a = fma2(a, wr[o], sum39[o]);
        a = relu2(a);
        const u64* wm = s.wmvd + i * 16;
        #pragma unroll
        for (int ii = 0; ii < 8; ii++) {
            macc[ii] = fma2(macc[ii], wm[ii], a);
            vacc[ii] = fma2(vacc[ii], wm[8 + ii], a);
        }
    }

    // reparameterization + output of means / log_var / z
    float* om = out + (size_t)Bn * 12;
    float* ol = out + (size_t)Bn * 20;
    float* oz = out + (size_t)Bn * 28;
    float zx[8], zy[8];
    #pragma unroll
    for (int ii = 0; ii < 8; ii++) {
        float mx, my, lx, ly;
        unpack2(macc[ii], mx, my);
        unpack2(vacc[ii], lx, ly);
        float ex = eps[(size_t)r0 * 8 + ii];
        float ey = eps[(size_t)r1 * 8 + ii];
        zx[ii] = fmaf(ex, __expf(0.5f * lx), mx);
        zy[ii] = fmaf(ey, __expf(0.5f * ly), my);
        om[(size_t)r0 * 8 + ii] = mx;  om[(size_t)r1 * 8 + ii] = my;
        ol[(size_t)r0 * 8 + ii] = lx;  ol[(size_t)r1 * 8 + ii] = ly;
        oz[(size_t)r0 * 8 + ii] = zx[ii]; oz[(size_t)r1 * 8 + ii] = zy[ii];
    }

    // decoder
    const int OID[12] = {0,1,2,3,10,11,12,13,14,18,22,26};
    u64 inp[20];
    #pragma unroll
    for (int tt = 0; tt < 12; tt++)
        inp[tt] = pack2(initial_c[(size_t)r0 * 30 + OID[tt]],
                        initial_c[(size_t)r1 * 30 + OID[tt]]);
    #pragma unroll
    for (int u = 0; u < 8; u++) inp[12 + u] = pack2(zx[u], zy[u]);

    u64 oacc[12];
    #pragma unroll
    for (int oo = 0; oo < 12; oo++) oacc[oo] = s.bd2d[oo];
    #pragma unroll 4
    for (int h = 0; h < 32; h++) {
        u64 a = s.bd1d[h];
        const u64* wr = s.wd1d + h * 20;
        #pragma unroll
        for (int tt = 0; tt < 20; tt++) a = fma2(a, wr[tt], inp[tt]);
        a = relu2(a);
        const u64* w2 = s.wd2d + h * 12;
        #pragma unroll
        for (int oo = 0; oo < 12; oo++) oacc[oo] = fma2(oacc[oo], w2[oo], a);
    }
    #pragma unroll
    for (int oo = 0; oo < 12; oo++) {
        float ax, ay; unpack2(oacc[oo], ax, ay);
        out[(size_t)r0 * 12 + oo] = 1.f / (1.f + __expf(-ax));
        out[(size_t)r1 * 12 + oo] = 1.f / (1.f + __expf(-ay));
    }
}

extern "C" void kernel_launch(void* const* d_in, const int* in_sizes, int n_in,
                              void* d_out, int out_size) {
    const float* initial_c = (const float*)d_in[0];
    // d_in[1] = initial_s : unused by the reference
    const float* current_c = (const float*)d_in[2];
    const float* eps       = (const float*)d_in[3];
    const float* W1  = (const float*)d_in[4];
    const float* b1  = (const float*)d_in[5];
    const float* W2  = (const float*)d_in[6];
    const float* b2  = (const float*)d_in[7];
    const float* W3  = (const float*)d_in[8];
    const float* b3  = (const float*)d_in[9];
    const float* Wm  = (const float*)d_in[10];
    const float* bm  = (const float*)d_in[11];
    const float* Wv  = (const float*)d_in[12];
    const float* bv  = (const float*)d_in[13];
    const float* Wd1 = (const float*)d_in[14];
    const float* bd1 = (const float*)d_in[15];
    const float* Wd2 = (const float*)d_in[16];
    const float* bd2 = (const float*)d_in[17];
    float* out = (float*)d_out;

    const int B = in_sizes[0] / 30;
    const int threads = B / 2;
    const int blocks = (threads + NT - 1) / NT;
    const int smem_bytes = (int)sizeof(Smem);

    cudaFuncSetAttribute(vae_kernel, cudaFuncAttributeMaxDynamicSharedMemorySize, smem_bytes);
    vae_kernel<<<blocks, NT, smem_bytes>>>(
        initial_c, current_c, eps,
        W1, b1, W2, b2, W3, b3, Wm, bm, Wv, bv, Wd1, bd1, Wd2, bd2,
        out, B);
}

// round 5
// speedup vs baseline: 1.0975x; 1.0975x over previous
#include <cuda_runtime.h>
#include <cstdint>

typedef unsigned long long u64;

// ---------- f32x2 packed helpers (sm_103a FFMA2 path, PTX-only) ----------
__device__ __forceinline__ u64 pack2(float x, float y) {
    u64 r; asm("mov.b64 %0, {%1,%2};" : "=l"(r) : "f"(x), "f"(y)); return r;
}
__device__ __forceinline__ void unpack2(u64 v, float& x, float& y) {
    asm("mov.b64 {%0,%1}, %2;" : "=f"(x), "=f"(y) : "l"(v));
}
// fma2(acc, b, c) = b*c + acc
__device__ __forceinline__ u64 fma2(u64 acc, u64 b, u64 c) {
    u64 d; asm("fma.rn.f32x2 %0, %1, %2, %3;" : "=l"(d) : "l"(b), "l"(c), "l"(acc)); return d;
}
__device__ __forceinline__ u64 add2(u64 a, u64 b) {
    u64 d; asm("add.rn.f32x2 %0, %1, %2;" : "=l"(d) : "l"(a), "l"(b)); return d;
}
__device__ __forceinline__ u64 relu2(u64 a) {
    float x, y; unpack2(a, x, y);
    return pack2(fmaxf(x, 0.f), fmaxf(y, 0.f));
}
__device__ __forceinline__ u64 dup(float w) { return pack2(w, w); }

// ---------- shared-memory weight cache (dup pairs, 16B-aligned rows for LDS.128) ----------
struct __align__(16) Smem {
    u64 w2d[128 * 40];   // [j][o]: o<39 dup(W2[o][j]), o=39 zero. chunks {0..19},{20..39}
    u64 w3d[128 * 40];   // [i][o]: o<39 dup(W3[i][o]), o=39 dup(b3[i])  (b3 folded, sum40[39]=1)
    u64 wmvd[128 * 16];  // [i][0..7]=dup(Wm[ii][i]), [8..15]=dup(Wv[ii][i])
    u64 wd1d[32 * 20];   // [h][t] = dup(Wd1[h][5+t])
    u64 wd2d[32 * 12];   // [h][o] = dup(Wd2[o][h])
    u64 b2d[40];         // dup(b2[o]), [39]=0
    u64 bmd[8];
    u64 bvd[8];
    u64 bd1d[32];        // dup(bd1[h] + Wd1[h][0])   (node-0 one-hot folded)
    u64 bd2d[12];
    float4 bw1[4 * 128]; // [e][j] = {b1[j]+W1[j][0]+W1[j][6+e], W1[j][10], W1[j][11], W1[j][12]}
};

#define NT 128

__global__ void __launch_bounds__(NT) vae_kernel(
    const float* __restrict__ initial_c,
    const float* __restrict__ current_c,
    const float* __restrict__ eps,
    const float* __restrict__ W1, const float* __restrict__ b1,
    const float* __restrict__ W2, const float* __restrict__ b2,
    const float* __restrict__ W3, const float* __restrict__ b3,
    const float* __restrict__ Wm, const float* __restrict__ bm,
    const float* __restrict__ Wv, const float* __restrict__ bv,
    const float* __restrict__ Wd1, const float* __restrict__ bd1,
    const float* __restrict__ Wd2, const float* __restrict__ bd2,
    float* __restrict__ out, int Bn)
{
    extern __shared__ unsigned char smem_raw[];
    Smem& s = *reinterpret_cast<Smem*>(smem_raw);
    const int tid = threadIdx.x;

    // ---------------- build weight cache ----------------
    for (int idx = tid; idx < 128 * 40; idx += NT) {
        int j = idx / 40, o = idx % 40;
        s.w2d[idx] = (o < 39) ? dup(W2[o * 128 + j]) : 0ull;
    }
    for (int idx = tid; idx < 128 * 40; idx += NT) {
        int i = idx / 40, o = idx % 40;
        s.w3d[idx] = (o < 39) ? dup(W3[i * 39 + o]) : dup(b3[i]);
    }
    for (int idx = tid; idx < 128 * 16; idx += NT) {
        int i = idx / 16, ii = idx % 16;
        s.wmvd[idx] = (ii < 8) ? dup(Wm[ii * 128 + i]) : dup(Wv[(ii - 8) * 128 + i]);
    }
    for (int idx = tid; idx < 32 * 20; idx += NT) {
        int h = idx / 20, t = idx % 20;
        s.wd1d[idx] = dup(Wd1[h * 25 + 5 + t]);
    }
    for (int idx = tid; idx < 32 * 12; idx += NT) {
        int h = idx / 12, o = idx % 12;
        s.wd2d[idx] = dup(Wd2[o * 32 + h]);
    }
    for (int idx = tid; idx < 40; idx += NT)
        s.b2d[idx] = (idx < 39) ? dup(b2[idx]) : 0ull;
    if (tid < 8) { s.bmd[tid] = dup(bm[tid]); s.bvd[tid] = dup(bv[tid]); }
    for (int idx = tid; idx < 32; idx += NT)
        s.bd1d[idx] = dup(bd1[idx] + Wd1[idx * 25 + 0]);
    for (int idx = tid; idx < 12; idx += NT)
        s.bd2d[idx] = dup(bd2[idx]);
    for (int idx = tid; idx < 512; idx += NT) {
        int e = idx >> 7, j = idx & 127;
        s.bw1[idx] = make_float4(b1[j] + W1[j * 13 + 0] + W1[j * 13 + 6 + e],
                                 W1[j * 13 + 10], W1[j * 13 + 11], W1[j * 13 + 12]);
    }
    __syncthreads();

    // ---------------- per-thread: 2 rows ----------------
    const int t = blockIdx.x * NT + tid;
    const int r0 = 2 * t;
    if (r0 >= Bn) return;
    const int r1 = r0 + 1;

    const int PRED[4][3] = {{0,10,14},{1,11,18},{2,12,22},{3,13,26}};
    float px[4][3], py[4][3];
    #pragma unroll
    for (int e = 0; e < 4; e++)
        #pragma unroll
        for (int k = 0; k < 3; k++) {
            px[e][k] = current_c[(size_t)r0 * 30 + PRED[e][k]];
            py[e][k] = current_c[(size_t)r1 * 30 + PRED[e][k]];
        }

    // ------- message passing: sum40 = sum_e relu(W2 @ relu(W1p@pred + bias1e) + b2) -------
    u64 sum40[40];
    #pragma unroll
    for (int c = 0; c < 2; c++) {
        const int ob = c * 20;
        #pragma unroll
        for (int e = 0; e < 4; e++) {
            u64 acc[20];
            {
                const ulonglong2* bb = (const ulonglong2*)(s.b2d + ob);
                #pragma unroll
                for (int p = 0; p < 10; p++) { ulonglong2 b = bb[p]; acc[2*p] = b.x; acc[2*p+1] = b.y; }
            }
            #pragma unroll 4
            for (int j = 0; j < 128; j++) {
                float4 bw = s.bw1[e * 128 + j];
                float hx = fmaf(bw.y, px[e][0], bw.x);
                float hy = fmaf(bw.y, py[e][0], bw.x);
                hx = fmaf(bw.z, px[e][1], hx);
                hy = fmaf(bw.z, py[e][1], hy);
                hx = fmaf(bw.w, px[e][2], hx);
                hy = fmaf(bw.w, py[e][2], hy);
                hx = fmaxf(hx, 0.f); hy = fmaxf(hy, 0.f);
                u64 h2 = pack2(hx, hy);
                const ulonglong2* wr = (const ulonglong2*)(s.w2d + j * 40 + ob);
                #pragma unroll
                for (int p = 0; p < 10; p++) {
                    ulonglong2 w = wr[p];
                    acc[2*p]   = fma2(acc[2*p],   w.x, h2);
                    acc[2*p+1] = fma2(acc[2*p+1], w.y, h2);
                }
            }
            #pragma unroll
            for (int oo = 0; oo < 20; oo++) {
                u64 r = relu2(acc[oo]);
                sum40[ob + oo] = (e == 0) ? r : add2(sum40[ob + oo], r);
            }
        }
    }
    sum40[39] = pack2(1.f, 1.f);   // multiplies the folded b3 slot in w3d

    // ------- layer3 + means/log_var fused -------
    u64 macc[8], vacc[8];
    #pragma unroll
    for (int ii = 0; ii < 8; ii++) { macc[ii] = s.bmd[ii]; vacc[ii] = s.bvd[ii]; }
    #pragma unroll 2
    for (int i = 0; i < 128; i++) {
        const ulonglong2* wr = (const ulonglong2*)(s.w3d + i * 40);
        u64 aA = 0ull, aB = 0ull;
        #pragma unroll
        for (int p = 0; p < 20; p++) {
            ulonglong2 w = wr[p];
            aA = fma2(aA, w.x, sum40[2*p]);
            aB = fma2(aB, w.y, sum40[2*p+1]);
        }
        u64 a = relu2(add2(aA, aB));
        const ulonglong2* wm = (const ulonglong2*)(s.wmvd + i * 16);
        #pragma unroll
        for (int k = 0; k < 4; k++) {
            ulonglong2 w = wm[k];
            macc[2*k]   = fma2(macc[2*k],   w.x, a);
            macc[2*k+1] = fma2(macc[2*k+1], w.y, a);
        }
        #pragma unroll
        for (int k = 0; k < 4; k++) {
            ulonglong2 w = wm[4 + k];
            vacc[2*k]   = fma2(vacc[2*k],   w.x, a);
            vacc[2*k+1] = fma2(vacc[2*k+1], w.y, a);
        }
    }

    // ------- reparameterization + vectorized output of means / log_var / z -------
    float* om = out + (size_t)Bn * 12;
    float* ol = out + (size_t)Bn * 20;
    float* oz = out + (size_t)Bn * 28;
    float mxv[2][8], lxv[2][8], zv[2][8];
    {
        const float4* e0 = (const float4*)(eps + (size_t)r0 * 8);
        const float4* e1 = (const float4*)(eps + (size_t)r1 * 8);
        float ex[8], ey[8];
        float4 q;
        q = e0[0]; ex[0]=q.x; ex[1]=q.y; ex[2]=q.z; ex[3]=q.w;
        q = e0[1]; ex[4]=q.x; ex[5]=q.y; ex[6]=q.z; ex[7]=q.w;
        q = e1[0]; ey[0]=q.x; ey[1]=q.y; ey[2]=q.z; ey[3]=q.w;
        q = e1[1]; ey[4]=q.x; ey[5]=q.y; ey[6]=q.z; ey[7]=q.w;
        #pragma unroll
        for (int ii = 0; ii < 8; ii++) {
            float mx, my, lx, ly;
            unpack2(macc[ii], mx, my);
            unpack2(vacc[ii], lx, ly);
            mxv[0][ii] = mx; mxv[1][ii] = my;
            lxv[0][ii] = lx; lxv[1][ii] = ly;
            zv[0][ii] = fmaf(ex[ii], __expf(0.5f * lx), mx);
            zv[1][ii] = fmaf(ey[ii], __expf(0.5f * ly), my);
        }
        #pragma unroll
        for (int rr = 0; rr < 2; rr++) {
            const size_t rb = (size_t)(r0 + rr) * 8;
            ((float4*)(om + rb))[0] = make_float4(mxv[rr][0], mxv[rr][1], mxv[rr][2], mxv[rr][3]);
            ((float4*)(om + rb))[1] = make_float4(mxv[rr][4], mxv[rr][5], mxv[rr][6], mxv[rr][7]);
            ((float4*)(ol + rb))[0] = make_float4(lxv[rr][0], lxv[rr][1], lxv[rr][2], lxv[rr][3]);
            ((float4*)(ol + rb))[1] = make_float4(lxv[rr][4], lxv[rr][5], lxv[rr][6], lxv[rr][7]);
            ((float4*)(oz + rb))[0] = make_float4(zv[rr][0], zv[rr][1], zv[rr][2], zv[rr][3]);
            ((float4*)(oz + rb))[1] = make_float4(zv[rr][4], zv[rr][5], zv[rr][6], zv[rr][7]);
        }
    }

    // ------- decoder -------
    const int OID[12] = {0,1,2,3,10,11,12,13,14,18,22,26};
    u64 inp[20];
    #pragma unroll
    for (int tt = 0; tt < 12; tt++)
        inp[tt] = pack2(initial_c[(size_t)r0 * 30 + OID[tt]],
                        initial_c[(size_t)r1 * 30 + OID[tt]]);
    #pragma unroll
    for (int u = 0; u < 8; u++) inp[12 + u] = pack2(zv[0][u], zv[1][u]);

    u64 oacc[12];
    {
        const ulonglong2* bb = (const ulonglong2*)(s.bd2d);
        #pragma unroll
        for (int p = 0; p < 6; p++) { ulonglong2 b = bb[p]; oacc[2*p] = b.x; oacc[2*p+1] = b.y; }
    }
    #pragma unroll 4
    for (int h = 0; h < 32; h++) {
        const ulonglong2* wr = (const ulonglong2*)(s.wd1d + h * 20);
        u64 aA = s.bd1d[h], aB = 0ull;
        #pragma unroll
        for (int p = 0; p < 10; p++) {
            ulonglong2 w = wr[p];
            aA = fma2(aA, w.x, inp[2*p]);
            aB = fma2(aB, w.y, inp[2*p+1]);
        }
        u64 a = relu2(add2(aA, aB));
        const ulonglong2* w2 = (const ulonglong2*)(s.wd2d + h * 12);
        #pragma unroll
        for (int p = 0; p < 6; p++) {
            ulonglong2 w = w2[p];
            oacc[2*p]   = fma2(oacc[2*p],   w.x, a);
            oacc[2*p+1] = fma2(oacc[2*p+1], w.y, a);
        }
    }
    {
        float r0v[12], r1v[12];
        #pragma unroll
        for (int oo = 0; oo < 12; oo++) {
            float ax, ay; unpack2(oacc[oo], ax, ay);
            r0v[oo] = 1.f / (1.f + __expf(-ax));
            r1v[oo] = 1.f / (1.f + __expf(-ay));
        }
        float4* o0 = (float4*)(out + (size_t)r0 * 12);
        float4* o1 = (float4*)(out + (size_t)r1 * 12);
        o0[0] = make_float4(r0v[0], r0v[1], r0v[2],  r0v[3]);
        o0[1] = make_float4(r0v[4], r0v[5], r0v[6],  r0v[7]);
        o0[2] = make_float4(r0v[8], r0v[9], r0v[10], r0v[11]);
        o1[0] = make_float4(r1v[0], r1v[1], r1v[2],  r1v[3]);
        o1[1] = make_float4(r1v[4], r1v[5], r1v[6],  r1v[7]);
        o1[2] = make_float4(r1v[8], r1v[9], r1v[10], r1v[11]);
    }
}

extern "C" void kernel_launch(void* const* d_in, const int* in_sizes, int n_in,
                              void* d_out, int out_size) {
    const float* initial_c = (const float*)d_in[0];
    // d_in[1] = initial_s : unused by the reference
    const float* current_c = (const float*)d_in[2];
    const float* eps       = (const float*)d_in[3];
    const float* W1  = (const float*)d_in[4];
    const float* b1  = (const float*)d_in[5];
    const float* W2  = (const float*)d_in[6];
    const float* b2  = (const float*)d_in[7];
    const float* W3  = (const float*)d_in[8];
    const float* b3  = (const float*)d_in[9];
    const float* Wm  = (const float*)d_in[10];
    const float* bm  = (const float*)d_in[11];
    const float* Wv  = (const float*)d_in[12];
    const float* bv  = (const float*)d_in[13];
    const float* Wd1 = (const float*)d_in[14];
    const float* bd1 = (const float*)d_in[15];
    const float* Wd2 = (const float*)d_in[16];
    const float* bd2 = (const float*)d_in[17];
    float* out = (float*)d_out;

    const int B = in_sizes[0] / 30;
    const int threads = B / 2;
    const int blocks = (threads + NT - 1) / NT;
    const int smem_bytes = (int)sizeof(Smem);

    cudaFuncSetAttribute(vae_kernel, cudaFuncAttributeMaxDynamicSharedMemorySize, smem_bytes);
    vae_kernel<<<blocks, NT, smem_bytes>>>(
        initial_c, current_c, eps,
        W1, b1, W2, b2, W3, b3, Wm, bm, Wv, bv, Wd1, bd1, Wd2, bd2,
        out, B);
}

// round 8
// speedup vs baseline: 1.6022x; 1.4599x over previous
#include <cuda_runtime.h>
#include <cstdint>

typedef unsigned long long u64;

// ---------- f32x2 packed helpers (sm_103a FFMA2 path, PTX-only) ----------
__device__ __forceinline__ u64 pack2(float x, float y) {
    u64 r; asm("mov.b64 %0, {%1,%2};" : "=l"(r) : "f"(x), "f"(y)); return r;
}
__device__ __forceinline__ void unpack2(u64 v, float& x, float& y) {
    asm("mov.b64 {%0,%1}, %2;" : "=f"(x), "=f"(y) : "l"(v));
}
// fma2(acc, b, c) = b*c + acc
__device__ __forceinline__ u64 fma2(u64 acc, u64 b, u64 c) {
    u64 d; asm("fma.rn.f32x2 %0, %1, %2, %3;" : "=l"(d) : "l"(b), "l"(c), "l"(acc)); return d;
}
__device__ __forceinline__ u64 add2(u64 a, u64 b) {
    u64 d; asm("add.rn.f32x2 %0, %1, %2;" : "=l"(d) : "l"(a), "l"(b)); return d;
}
__device__ __forceinline__ u64 relu2(u64 a) {
    float x, y; unpack2(a, x, y);
    return pack2(fmaxf(x, 0.f), fmaxf(y, 0.f));
}
__device__ __forceinline__ float hadd2(u64 a) {
    float x, y; unpack2(a, x, y); return x + y;
}

// ---------- shared weights: NATURAL float2 output-pairs (no duplication) ----------
// f32x2 lanes now carry (output o, output o+1); activations get dup'd in registers.
struct __align__(16) Smem {
    float2 w2p[128 * 20];  // [j*20+p] = (W2[2p][j], W2[2p+1][j]); p=19 -> (W2[38][j], 0)
    float2 w3p[128 * 20];  // [i*20+p] = (W3[i][2p], W3[i][2p+1]); p=19 -> (W3[i][38], b3[i])
    float2 wmv[128 * 8];   // [i*8+k]: k<4 (Wm[2k][i],Wm[2k+1][i]); k>=4 (Wv[2(k-4)][i],Wv[2(k-4)+1][i])
    float4 bw1[4 * 128];   // [e*128+j] = {b1[j]+W1[j][0]+W1[j][6+e], W1[j][10..12]}
    float2 wd1p[32 * 10];  // [h*10+p] = (Wd1[h][5+2p], Wd1[h][5+2p+1])
    float2 wd2p[32 * 6];   // [h*6+o]  = (Wd2[2o][h], Wd2[2o+1][h])
    float2 b2p[20];        // (b2[2p], b2[2p+1]); p=19 -> (b2[38], 0)
    float2 bmv[8];         // k<4 (bm[2k],bm[2k+1]); k>=4 (bv...)
    float2 bd2p[6];
    float  bd1s[32];       // bd1[h] + Wd1[h][0]   (node-0 one-hot folded)
};

#define NT 128

__global__ void __launch_bounds__(NT) vae_kernel(
    const float* __restrict__ initial_c,
    const float* __restrict__ current_c,
    const float* __restrict__ eps,
    const float* __restrict__ W1, const float* __restrict__ b1,
    const float* __restrict__ W2, const float* __restrict__ b2,
    const float* __restrict__ W3, const float* __restrict__ b3,
    const float* __restrict__ Wm, const float* __restrict__ bm,
    const float* __restrict__ Wv, const float* __restrict__ bv,
    const float* __restrict__ Wd1, const float* __restrict__ bd1,
    const float* __restrict__ Wd2, const float* __restrict__ bd2,
    float* __restrict__ out, int Bn)
{
    extern __shared__ unsigned char smem_raw[];
    Smem& s = *reinterpret_cast<Smem*>(smem_raw);
    const int tid = threadIdx.x;

    // ---------------- build weight cache ----------------
    for (int idx = tid; idx < 128 * 20; idx += NT) {
        int j = idx / 20, p = idx % 20;
        float a = W2[(2 * p) * 128 + j];
        float b = (2 * p + 1 < 39) ? W2[(2 * p + 1) * 128 + j] : 0.f;
        s.w2p[idx] = make_float2(a, b);
    }
    for (int idx = tid; idx < 128 * 20; idx += NT) {
        int i = idx / 20, p = idx % 20;
        float a = W3[i * 39 + 2 * p];
        float b = (2 * p + 1 < 39) ? W3[i * 39 + 2 * p + 1] : b3[i];
        s.w3p[idx] = make_float2(a, b);
    }
    for (int idx = tid; idx < 128 * 8; idx += NT) {
        int i = idx / 8, k = idx % 8;
        s.wmv[idx] = (k < 4)
            ? make_float2(Wm[(2 * k) * 128 + i], Wm[(2 * k + 1) * 128 + i])
            : make_float2(Wv[(2 * (k - 4)) * 128 + i], Wv[(2 * (k - 4) + 1) * 128 + i]);
    }
    for (int idx = tid; idx < 512; idx += NT) {
        int e = idx >> 7, j = idx & 127;
        s.bw1[idx] = make_float4(b1[j] + W1[j * 13 + 0] + W1[j * 13 + 6 + e],
                                 W1[j * 13 + 10], W1[j * 13 + 11], W1[j * 13 + 12]);
    }
    for (int idx = tid; idx < 320; idx += NT) {
        int h = idx / 10, p = idx % 10;
        s.wd1p[idx] = make_float2(Wd1[h * 25 + 5 + 2 * p], Wd1[h * 25 + 5 + 2 * p + 1]);
    }
    for (int idx = tid; idx < 192; idx += NT) {
        int h = idx / 6, o = idx % 6;
        s.wd2p[idx] = make_float2(Wd2[(2 * o) * 32 + h], Wd2[(2 * o + 1) * 32 + h]);
    }
    if (tid < 20) s.b2p[tid] = make_float2(b2[2 * tid], (2 * tid + 1 < 39) ? b2[2 * tid + 1] : 0.f);
    if (tid >= 32 && tid < 40) {
        int k = tid - 32;
        s.bmv[k] = (k < 4) ? make_float2(bm[2 * k], bm[2 * k + 1])
                           : make_float2(bv[2 * (k - 4)], bv[2 * (k - 4) + 1]);
    }
    if (tid >= 64 && tid < 70) { int o = tid - 64; s.bd2p[o] = make_float2(bd2[2 * o], bd2[2 * o + 1]); }
    if (tid >= 96 && tid < 128) { int h = tid - 96; s.bd1s[h] = bd1[h] + Wd1[h * 25 + 0]; }
    __syncthreads();

    // ---------------- per-thread: 2 rows ----------------
    const int t = blockIdx.x * NT + tid;
    const int r0 = 2 * t;
    if (r0 >= Bn) return;
    const int r1 = r0 + 1;

    const int PRED[4][3] = {{0,10,14},{1,11,18},{2,12,22},{3,13,26}};
    float px[4][3], py[4][3];
    #pragma unroll
    for (int e = 0; e < 4; e++)
        #pragma unroll
        for (int k = 0; k < 3; k++) {
            px[e][k] = current_c[(size_t)r0 * 30 + PRED[e][k]];
            py[e][k] = current_c[(size_t)r1 * 30 + PRED[e][k]];
        }

    // ------- message passing: per-row sums over output pairs -------
    u64 sum0[20], sum1[20];
    #pragma unroll
    for (int c = 0; c < 2; c++) {
        const int pb = c * 10;
        #pragma unroll
        for (int e = 0; e < 4; e++) {
            u64 a0[10], a1[10];
            {
                const ulonglong2* bb = (const ulonglong2*)(s.b2p + pb);
                #pragma unroll
                for (int q = 0; q < 5; q++) {
                    ulonglong2 b = bb[q];
                    a0[2*q] = b.x; a0[2*q+1] = b.y;
                    a1[2*q] = b.x; a1[2*q+1] = b.y;
                }
            }
            #pragma unroll 4
            for (int j = 0; j < 128; j++) {
                float4 bw = s.bw1[e * 128 + j];
                float h0 = fmaf(bw.y, px[e][0], bw.x);
                float h1 = fmaf(bw.y, py[e][0], bw.x);
                h0 = fmaf(bw.z, px[e][1], h0);
                h1 = fmaf(bw.z, py[e][1], h1);
                h0 = fmaf(bw.w, px[e][2], h0);
                h1 = fmaf(bw.w, py[e][2], h1);
                h0 = fmaxf(h0, 0.f); h1 = fmaxf(h1, 0.f);
                u64 h20 = pack2(h0, h0), h21 = pack2(h1, h1);
                const ulonglong2* wr = (const ulonglong2*)(s.w2p + j * 20 + pb);
                #pragma unroll
                for (int q = 0; q < 5; q++) {
                    ulonglong2 w = wr[q];
                    a0[2*q]   = fma2(a0[2*q],   w.x, h20);
                    a1[2*q]   = fma2(a1[2*q],   w.x, h21);
                    a0[2*q+1] = fma2(a0[2*q+1], w.y, h20);
                    a1[2*q+1] = fma2(a1[2*q+1], w.y, h21);
                }
            }
            #pragma unroll
            for (int p = 0; p < 10; p++) {
                u64 r0v = relu2(a0[p]), r1v = relu2(a1[p]);
                if (e == 0) { sum0[pb + p] = r0v; sum1[pb + p] = r1v; }
                else        { sum0[pb + p] = add2(sum0[pb + p], r0v);
                              sum1[pb + p] = add2(sum1[pb + p], r1v); }
            }
        }
    }
    // pair 19 slot .y multiplies folded b3 -> set to 1
    { float x, y; unpack2(sum0[19], x, y); sum0[19] = pack2(x, 1.f);
      unpack2(sum1[19], x, y); sum1[19] = pack2(x, 1.f); }

    // ------- layer3 + means/log_var fused -------
    u64 m0[4], v0[4], m1[4], v1[4];
    {
        const ulonglong2* bb = (const ulonglong2*)(s.bmv);
        ulonglong2 u;
        u = bb[0]; m0[0]=u.x; m0[1]=u.y; m1[0]=u.x; m1[1]=u.y;
        u = bb[1]; m0[2]=u.x; m0[3]=u.y; m1[2]=u.x; m1[3]=u.y;
        u = bb[2]; v0[0]=u.x; v0[1]=u.y; v1[0]=u.x; v1[1]=u.y;
        u = bb[3]; v0[2]=u.x; v0[3]=u.y; v1[2]=u.x; v1[3]=u.y;
    }
    #pragma unroll 2
    for (int i = 0; i < 128; i++) {
        const ulonglong2* wr = (const ulonglong2*)(s.w3p + i * 20);
        u64 aA0 = 0ull, aB0 = 0ull, aA1 = 0ull, aB1 = 0ull;
        #pragma unroll
        for (int q = 0; q < 10; q++) {
            ulonglong2 w = wr[q];
            aA0 = fma2(aA0, w.x, sum0[2*q]);
            aB0 = fma2(aB0, w.y, sum0[2*q+1]);
            aA1 = fma2(aA1, w.x, sum1[2*q]);
            aB1 = fma2(aB1, w.y, sum1[2*q+1]);
        }
        float a0s = fmaxf(hadd2(add2(aA0, aB0)), 0.f);
        float a1s = fmaxf(hadd2(add2(aA1, aB1)), 0.f);
        u64 a20 = pack2(a0s, a0s), a21 = pack2(a1s, a1s);
        const ulonglong2* wm = (const ulonglong2*)(s.wmv + i * 8);
        ulonglong2 w;
        w = wm[0];
        m0[0] = fma2(m0[0], w.x, a20); m1[0] = fma2(m1[0], w.x, a21);
        m0[1] = fma2(m0[1], w.y, a20); m1[1] = fma2(m1[1], w.y, a21);
        w = wm[1];
        m0[2] = fma2(m0[2], w.x, a20); m1[2] = fma2(m1[2], w.x, a21);
        m0[3] = fma2(m0[3], w.y, a20); m1[3] = fma2(m1[3], w.y, a21);
        w = wm[2];
        v0[0] = fma2(v0[0], w.x, a20); v1[0] = fma2(v1[0], w.x, a21);
        v0[1] = fma2(v0[1], w.y, a20); v1[1] = fma2(v1[1], w.y, a21);
        w = wm[3];
        v0[2] = fma2(v0[2], w.x, a20); v1[2] = fma2(v1[2], w.x, a21);
        v0[3] = fma2(v0[3], w.y, a20); v1[3] = fma2(v1[3], w.y, a21);
    }

    // ------- reparameterization + vectorized outputs -------
    float* om = out + (size_t)Bn * 12;
    float* ol = out + (size_t)Bn * 20;
    float* oz = out + (size_t)Bn * 28;
    float mv0[8], mv1[8], lv0[8], lv1[8], z0[8], z1[8];
    #pragma unroll
    for (int k = 0; k < 4; k++) {
        unpack2(m0[k], mv0[2*k], mv0[2*k+1]);
        unpack2(m1[k], mv1[2*k], mv1[2*k+1]);
        unpack2(v0[k], lv0[2*k], lv0[2*k+1]);
        unpack2(v1[k], lv1[2*k], lv1[2*k+1]);
    }
    {
        const float4* e0 = (const float4*)(eps + (size_t)r0 * 8);
        const float4* e1 = (const float4*)(eps + (size_t)r1 * 8);
        float ex[8], ey[8];
        float4 q;
        q = e0[0]; ex[0]=q.x; ex[1]=q.y; ex[2]=q.z; ex[3]=q.w;
        q = e0[1]; ex[4]=q.x; ex[5]=q.y; ex[6]=q.z; ex[7]=q.w;
        q = e1[0]; ey[0]=q.x; ey[1]=q.y; ey[2]=q.z; ey[3]=q.w;
        q = e1[1]; ey[4]=q.x; ey[5]=q.y; ey[6]=q.z; ey[7]=q.w;
        #pragma unroll
        for (int ii = 0; ii < 8; ii++) {
            z0[ii] = fmaf(ex[ii], __expf(0.5f * lv0[ii]), mv0[ii]);
            z1[ii] = fmaf(ey[ii], __expf(0.5f * lv1[ii]), mv1[ii]);
        }
        const size_t rb0 = (size_t)r0 * 8, rb1 = (size_t)r1 * 8;
        ((float4*)(om + rb0))[0] = make_float4(mv0[0], mv0[1], mv0[2], mv0[3]);
        ((float4*)(om + rb0))[1] = make_float4(mv0[4], mv0[5], mv0[6], mv0[7]);
        ((float4*)(om + rb1))[0] = make_float4(mv1[0], mv1[1], mv1[2], mv1[3]);
        ((float4*)(om + rb1))[1] = make_float4(mv1[4], mv1[5], mv1[6], mv1[7]);
        ((float4*)(ol + rb0))[0] = make_float4(lv0[0], lv0[1], lv0[2], lv0[3]);
        ((float4*)(ol + rb0))[1] = make_float4(lv0[4], lv0[5], lv0[6], lv0[7]);
        ((float4*)(ol + rb1))[0] = make_float4(lv1[0], lv1[1], lv1[2], lv1[3]);
        ((float4*)(ol + rb1))[1] = make_float4(lv1[4], lv1[5], lv1[6], lv1[7]);
        ((float4*)(oz + rb0))[0] = make_float4(z0[0], z0[1], z0[2], z0[3]);
        ((float4*)(oz + rb0))[1] = make_float4(z0[4], z0[5], z0[6], z0[7]);
        ((float4*)(oz + rb1))[0] = make_float4(z1[0], z1[1], z1[2], z1[3]);
        ((float4*)(oz + rb1))[1] = make_float4(z1[4], z1[5], z1[6], z1[7]);
    }

    // ------- decoder (input pairs over feature axis, per row) -------
    const int OID[12] = {0,1,2,3,10,11,12,13,14,18,22,26};
    u64 inp0[10], inp1[10];
    #pragma unroll
    for (int p = 0; p < 6; p++) {
        inp0[p] = pack2(initial_c[(size_t)r0 * 30 + OID[2*p]],
                        initial_c[(size_t)r0 * 30 + OID[2*p+1]]);
        inp1[p] = pack2(initial_c[(size_t)r1 * 30 + OID[2*p]],
                        initial_c[(size_t)r1 * 30 + OID[2*p+1]]);
    }
    #pragma unroll
    for (int u = 0; u < 4; u++) {
        inp0[6 + u] = pack2(z0[2*u], z0[2*u+1]);
        inp1[6 + u] = pack2(z1[2*u], z1[2*u+1]);
    }

    u64 oa0[6], oa1[6];
    {
        const ulonglong2* bb = (const ulonglong2*)(s.bd2p);
        #pragma unroll
        for (int q = 0; q < 3; q++) {
            ulonglong2 b = bb[q];
            oa0[2*q] = b.x; oa0[2*q+1] = b.y;
            oa1[2*q] = b.x; oa1[2*q+1] = b.y;
        }
    }
    #pragma unroll 4
    for (int h = 0; h < 32; h++) {
        const ulonglong2* wr = (const ulonglong2*)(s.wd1p + h * 10);
        u64 aA0 = 0ull, aB0 = 0ull, aA1 = 0ull, aB1 = 0ull;
        #pragma unroll
        for (int q = 0; q < 5; q++) {
            ulonglong2 w = wr[q];
            aA0 = fma2(aA0, w.x, inp0[2*q]);
            aB0 = fma2(aB0, w.y, inp0[2*q+1]);
            aA1 = fma2(aA1, w.x, inp1[2*q]);
            aB1 = fma2(aB1, w.y, inp1[2*q+1]);
        }
        float bias = s.bd1s[h];
        float a0s = fmaxf(bias + hadd2(add2(aA0, aB0)), 0.f);
        float a1s = fmaxf(bias + hadd2(add2(aA1, aB1)), 0.f);
        u64 a20 = pack2(a0s, a0s), a21 = pack2(a1s, a1s);
        const ulonglong2* w2r = (const ulonglong2*)(s.wd2p + h * 6);
        #pragma unroll
        for (int q = 0; q < 3; q++) {
            ulonglong2 w = w2r[q];
            oa0[2*q]   = fma2(oa0[2*q],   w.x, a20);
            oa1[2*q]   = fma2(oa1[2*q],   w.x, a21);
            oa0[2*q+1] = fma2(oa0[2*q+1], w.y, a20);
            oa1[2*q+1] = fma2(oa1[2*q+1], w.y, a21);
        }
    }
    {
        float r0v[12], r1v[12];
        #pragma unroll
        for (int q = 0; q < 6; q++) {
            float ax, ay;
            unpack2(oa0[q], ax, ay);
            r0v[2*q]   = 1.f / (1.f + __expf(-ax));
            r0v[2*q+1] = 1.f / (1.f + __expf(-ay));
            unpack2(oa1[q], ax, ay);
            r1v[2*q]   = 1.f / (1.f + __expf(-ax));
            r1v[2*q+1] = 1.f / (1.f + __expf(-ay));
        }
        float4* o0 = (float4*)(out + (size_t)r0 * 12);
        float4* o1 = (float4*)(out + (size_t)r1 * 12);
        o0[0] = make_float4(r0v[0], r0v[1], r0v[2],  r0v[3]);
        o0[1] = make_float4(r0v[4], r0v[5], r0v[6],  r0v[7]);
        o0[2] = make_float4(r0v[8], r0v[9], r0v[10], r0v[11]);
        o1[0] = make_float4(r1v[0], r1v[1], r1v[2],  r1v[3]);
        o1[1] = make_float4(r1v[4], r1v[5], r1v[6],  r1v[7]);
        o1[2] = make_float4(r1v[8], r1v[9], r1v[10], r1v[11]);
    }
}

extern "C" void kernel_launch(void* const* d_in, const int* in_sizes, int n_in,
                              void* d_out, int out_size) {
    const float* initial_c = (const float*)d_in[0];
    // d_in[1] = initial_s : unused by the reference
    const float* current_c = (const float*)d_in[2];
    const float* eps       = (const float*)d_in[3];
    const float* W1  = (const float*)d_in[4];
    const float* b1  = (const float*)d_in[5];
    const float* W2  = (const float*)d_in[6];
    const float* b2  = (const float*)d_in[7];
    const float* W3  = (const float*)d_in[8];
    const float* b3  = (const float*)d_in[9];
    const float* Wm  = (const float*)d_in[10];
    const float* bm  = (const float*)d_in[11];
    const float* Wv  = (const float*)d_in[12];
    const float* bv  = (const float*)d_in[13];
    const float* Wd1 = (const float*)d_in[14];
    const float* bd1 = (const float*)d_in[15];
    const float* Wd2 = (const float*)d_in[16];
    const float* bd2 = (const float*)d_in[17];
    float* out = (float*)d_out;

    const int B = in_sizes[0] / 30;
    const int threads = B / 2;
    const int blocks = (threads + NT - 1) / NT;
    const int smem_bytes = (int)sizeof(Smem);

    cudaFuncSetAttribute(vae_kernel, cudaFuncAttributeMaxDynamicSharedMemorySize, smem_bytes);
    vae_kernel<<<blocks, NT, smem_bytes>>>(
        initial_c, current_c, eps,
        W1, b1, W2, b2, W3, b3, Wm, bm, Wv, bv, Wd1, bd1, Wd2, bd2,
        out, B);
}

// round 10
// speedup vs baseline: 1.7777x; 1.1095x over previous
#include <cuda_runtime.h>
#include <cstdint>

typedef unsigned long long u64;

// ---------- f32x2 packed helpers (sm_103a FFMA2 path, PTX-only) ----------
__device__ __forceinline__ u64 pack2(float x, float y) {
    u64 r; asm("mov.b64 %0, {%1,%2};" : "=l"(r) : "f"(x), "f"(y)); return r;
}
__device__ __forceinline__ void unpack2(u64 v, float& x, float& y) {
    asm("mov.b64 {%0,%1}, %2;" : "=f"(x), "=f"(y) : "l"(v));
}
// fma2(acc, b, c) = b*c + acc
__device__ __forceinline__ u64 fma2(u64 acc, u64 b, u64 c) {
    u64 d; asm("fma.rn.f32x2 %0, %1, %2, %3;" : "=l"(d) : "l"(b), "l"(c), "l"(acc)); return d;
}
__device__ __forceinline__ u64 add2(u64 a, u64 b) {
    u64 d; asm("add.rn.f32x2 %0, %1, %2;" : "=l"(d) : "l"(a), "l"(b)); return d;
}
__device__ __forceinline__ u64 relu2(u64 a) {
    float x, y; unpack2(a, x, y);
    return pack2(fmaxf(x, 0.f), fmaxf(y, 0.f));
}
__device__ __forceinline__ float hadd2(u64 a) {
    float x, y; unpack2(a, x, y); return x + y;
}

// ---------- shared weights: NATURAL float2 output-pairs (no duplication) ----------
struct __align__(16) Smem {
    float2 w2p[128 * 20];  // [j*20+p] = (W2[2p][j], W2[2p+1][j]); p=19 -> (W2[38][j], 0)
    float2 w3p[128 * 20];  // [i*20+p] = (W3[i][2p], W3[i][2p+1]); p=19 -> (W3[i][38], b3[i])
    float2 wmv[128 * 8];   // [i*8+k]: k<4 (Wm[2k][i],Wm[2k+1][i]); k>=4 (Wv pairs)
    float4 bw1[4 * 128];   // [e*128+j] = {b1[j]+W1[j][0]+W1[j][6+e], W1[j][10..12]}
    float2 wd1p[32 * 10];  // [h*10+p] = (Wd1[h][5+2p], Wd1[h][5+2p+1])
    float2 wd2p[32 * 6];   // [h*6+o]  = (Wd2[2o][h], Wd2[2o+1][h])
    float2 b2p[20];        // (b2[2p], b2[2p+1]); p=19 -> (b2[38], 0)
    float2 bmv[8];         // k<4 (bm[2k],bm[2k+1]); k>=4 (bv...)
    float2 bd2p[6];
    float  bd1s[32];       // bd1[h] + Wd1[h][0]   (node-0 one-hot folded)
};

#define NT 128

__global__ void __launch_bounds__(NT, 3) vae_kernel(
    const float* __restrict__ initial_c,
    const float* __restrict__ current_c,
    const float* __restrict__ eps,
    const float* __restrict__ W1, const float* __restrict__ b1,
    const float* __restrict__ W2, const float* __restrict__ b2,
    const float* __restrict__ W3, const float* __restrict__ b3,
    const float* __restrict__ Wm, const float* __restrict__ bm,
    const float* __restrict__ Wv, const float* __restrict__ bv,
    const float* __restrict__ Wd1, const float* __restrict__ bd1,
    const float* __restrict__ Wd2, const float* __restrict__ bd2,
    float* __restrict__ out, int Bn)
{
    extern __shared__ unsigned char smem_raw[];
    Smem& s = *reinterpret_cast<Smem*>(smem_raw);
    const int tid = threadIdx.x;

    // ---------------- build weight cache ----------------
    for (int idx = tid; idx < 128 * 20; idx += NT) {
        int j = idx / 20, p = idx % 20;
        float a = W2[(2 * p) * 128 + j];
        float b = (2 * p + 1 < 39) ? W2[(2 * p + 1) * 128 + j] : 0.f;
        s.w2p[idx] = make_float2(a, b);
    }
    for (int idx = tid; idx < 128 * 20; idx += NT) {
        int i = idx / 20, p = idx % 20;
        float a = W3[i * 39 + 2 * p];
        float b = (2 * p + 1 < 39) ? W3[i * 39 + 2 * p + 1] : b3[i];
        s.w3p[idx] = make_float2(a, b);
    }
    for (int idx = tid; idx < 128 * 8; idx += NT) {
        int i = idx / 8, k = idx % 8;
        s.wmv[idx] = (k < 4)
            ? make_float2(Wm[(2 * k) * 128 + i], Wm[(2 * k + 1) * 128 + i])
            : make_float2(Wv[(2 * (k - 4)) * 128 + i], Wv[(2 * (k - 4) + 1) * 128 + i]);
    }
    for (int idx = tid; idx < 512; idx += NT) {
        int e = idx >> 7, j = idx & 127;
        s.bw1[idx] = make_float4(b1[j] + W1[j * 13 + 0] + W1[j * 13 + 6 + e],
                                 W1[j * 13 + 10], W1[j * 13 + 11], W1[j * 13 + 12]);
    }
    for (int idx = tid; idx < 320; idx += NT) {
        int h = idx / 10, p = idx % 10;
        s.wd1p[idx] = make_float2(Wd1[h * 25 + 5 + 2 * p], Wd1[h * 25 + 5 + 2 * p + 1]);
    }
    for (int idx = tid; idx < 192; idx += NT) {
        int h = idx / 6, o = idx % 6;
        s.wd2p[idx] = make_float2(Wd2[(2 * o) * 32 + h], Wd2[(2 * o + 1) * 32 + h]);
    }
    if (tid < 20) s.b2p[tid] = make_float2(b2[2 * tid], (2 * tid + 1 < 39) ? b2[2 * tid + 1] : 0.f);
    if (tid >= 32 && tid < 40) {
        int k = tid - 32;
        s.bmv[k] = (k < 4) ? make_float2(bm[2 * k], bm[2 * k + 1])
                           : make_float2(bv[2 * (k - 4)], bv[2 * (k - 4) + 1]);
    }
    if (tid >= 64 && tid < 70) { int o = tid - 64; s.bd2p[o] = make_float2(bd2[2 * o], bd2[2 * o + 1]); }
    if (tid >= 96 && tid < 128) { int h = tid - 96; s.bd1s[h] = bd1[h] + Wd1[h * 25 + 0]; }
    __syncthreads();

    // ---------------- per-thread: 2 rows ----------------
    const int t = blockIdx.x * NT + tid;
    const int r0 = 2 * t;
    if (r0 >= Bn) return;
    const int r1 = r0 + 1;
    const float* cc0 = current_c + (size_t)r0 * 30;
    const float* cc1 = current_c + (size_t)r1 * 30;

    // ------- message passing: per-row sums over output pairs -------
    // preds loaded per (c,e) inside the loop to minimize live registers
    u64 sum0[20], sum1[20];
    #pragma unroll
    for (int c = 0; c < 2; c++) {
        const int pb = c * 10;
        #pragma unroll
        for (int e = 0; e < 4; e++) {
            // predicate triplet for edge e: {e, 10+e, 14+4e}
            const int i0 = e, i1 = 10 + e, i2 = 14 + 4 * e;
            float p0x = cc0[i0], p1x = cc0[i1], p2x = cc0[i2];
            float p0y = cc1[i0], p1y = cc1[i1], p2y = cc1[i2];
            u64 a0[10], a1[10];
            {
                const ulonglong2* bb = (const ulonglong2*)(s.b2p + pb);
                #pragma unroll
                for (int q = 0; q < 5; q++) {
                    ulonglong2 b = bb[q];
                    a0[2*q] = b.x; a0[2*q+1] = b.y;
                    a1[2*q] = b.x; a1[2*q+1] = b.y;
                }
            }
            #pragma unroll 4
            for (int j = 0; j < 128; j++) {
                float4 bw = s.bw1[e * 128 + j];
                float h0 = fmaf(bw.y, p0x, bw.x);
                float h1 = fmaf(bw.y, p0y, bw.x);
                h0 = fmaf(bw.z, p1x, h0);
                h1 = fmaf(bw.z, p1y, h1);
                h0 = fmaf(bw.w, p2x, h0);
                h1 = fmaf(bw.w, p2y, h1);
                h0 = fmaxf(h0, 0.f); h1 = fmaxf(h1, 0.f);
                u64 h20 = pack2(h0, h0), h21 = pack2(h1, h1);
                const ulonglong2* wr = (const ulonglong2*)(s.w2p + j * 20 + pb);
                #pragma unroll
                for (int q = 0; q < 5; q++) {
                    ulonglong2 w = wr[q];
                    a0[2*q]   = fma2(a0[2*q],   w.x, h20);
                    a1[2*q]   = fma2(a1[2*q],   w.x, h21);
                    a0[2*q+1] = fma2(a0[2*q+1], w.y, h20);
                    a1[2*q+1] = fma2(a1[2*q+1], w.y, h21);
                }
            }
            #pragma unroll
            for (int p = 0; p < 10; p++) {
                u64 r0v = relu2(a0[p]), r1v = relu2(a1[p]);
                if (e == 0) { sum0[pb + p] = r0v; sum1[pb + p] = r1v; }
                else        { sum0[pb + p] = add2(sum0[pb + p], r0v);
                              sum1[pb + p] = add2(sum1[pb + p], r1v); }
            }
        }
    }
    // pair 19 slot .y multiplies folded b3 -> set to 1
    { float x, y; unpack2(sum0[19], x, y); sum0[19] = pack2(x, 1.f);
      unpack2(sum1[19], x, y); sum1[19] = pack2(x, 1.f); }

    // ------- layer3 + means/log_var fused -------
    u64 m0[4], v0[4], m1[4], v1[4];
    {
        const ulonglong2* bb = (const ulonglong2*)(s.bmv);
        ulonglong2 u;
        u = bb[0]; m0[0]=u.x; m0[1]=u.y; m1[0]=u.x; m1[1]=u.y;
        u = bb[1]; m0[2]=u.x; m0[3]=u.y; m1[2]=u.x; m1[3]=u.y;
        u = bb[2]; v0[0]=u.x; v0[1]=u.y; v1[0]=u.x; v1[1]=u.y;
        u = bb[3]; v0[2]=u.x; v0[3]=u.y; v1[2]=u.x; v1[3]=u.y;
    }
    #pragma unroll 2
    for (int i = 0; i < 128; i++) {
        const ulonglong2* wr = (const ulonglong2*)(s.w3p + i * 20);
        u64 aA0 = 0ull, aB0 = 0ull, aA1 = 0ull, aB1 = 0ull;
        #pragma unroll
        for (int q = 0; q < 10; q++) {
            ulonglong2 w = wr[q];
            aA0 = fma2(aA0, w.x, sum0[2*q]);
            aB0 = fma2(aB0, w.y, sum0[2*q+1]);
            aA1 = fma2(aA1, w.x, sum1[2*q]);
            aB1 = fma2(aB1, w.y, sum1[2*q+1]);
        }
        float a0s = fmaxf(hadd2(add2(aA0, aB0)), 0.f);
        float a1s = fmaxf(hadd2(add2(aA1, aB1)), 0.f);
        u64 a20 = pack2(a0s, a0s), a21 = pack2(a1s, a1s);
        const ulonglong2* wm = (const ulonglong2*)(s.wmv + i * 8);
        ulonglong2 w;
        w = wm[0];
        m0[0] = fma2(m0[0], w.x, a20); m1[0] = fma2(m1[0], w.x, a21);
        m0[1] = fma2(m0[1], w.y, a20); m1[1] = fma2(m1[1], w.y, a21);
        w = wm[1];
        m0[2] = fma2(m0[2], w.x, a20); m1[2] = fma2(m1[2], w.x, a21);
        m0[3] = fma2(m0[3], w.y, a20); m1[3] = fma2(m1[3], w.y, a21);
        w = wm[2];
        v0[0] = fma2(v0[0], w.x, a20); v1[0] = fma2(v1[0], w.x, a21);
        v0[1] = fma2(v0[1], w.y, a20); v1[1] = fma2(v1[1], w.y, a21);
        w = wm[3];
        v0[2] = fma2(v0[2], w.x, a20); v1[2] = fma2(v1[2], w.x, a21);
        v0[3] = fma2(v0[3], w.y, a20); v1[3] = fma2(v1[3], w.y, a21);
    }

    // ------- reparameterization + vectorized outputs -------
    float* om = out + (size_t)Bn * 12;
    float* ol = out + (size_t)Bn * 20;
    float* oz = out + (size_t)Bn * 28;
    float mv0[8], mv1[8], lv0[8], lv1[8], z0[8], z1[8];
    #pragma unroll
    for (int k = 0; k < 4; k++) {
        unpack2(m0[k], mv0[2*k], mv0[2*k+1]);
        unpack2(m1[k], mv1[2*k], mv1[2*k+1]);
        unpack2(v0[k], lv0[2*k], lv0[2*k+1]);
        unpack2(v1[k], lv1[2*k], lv1[2*k+1]);
    }
    {
        const float4* e0 = (const float4*)(eps + (size_t)r0 * 8);
        const float4* e1 = (const float4*)(eps + (size_t)r1 * 8);
        float ex[8], ey[8];
        float4 q;
        q = e0[0]; ex[0]=q.x; ex[1]=q.y; ex[2]=q.z; ex[3]=q.w;
        q = e0[1]; ex[4]=q.x; ex[5]=q.y; ex[6]=q.z; ex[7]=q.w;
        q = e1[0]; ey[0]=q.x; ey[1]=q.y; ey[2]=q.z; ey[3]=q.w;
        q = e1[1]; ey[4]=q.x; ey[5]=q.y; ey[6]=q.z; ey[7]=q.w;
        #pragma unroll
        for (int ii = 0; ii < 8; ii++) {
            z0[ii] = fmaf(ex[ii], __expf(0.5f * lv0[ii]), mv0[ii]);
            z1[ii] = fmaf(ey[ii], __expf(0.5f * lv1[ii]), mv1[ii]);
        }
        const size_t rb0 = (size_t)r0 * 8, rb1 = (size_t)r1 * 8;
        ((float4*)(om + rb0))[0] = make_float4(mv0[0], mv0[1], mv0[2], mv0[3]);
        ((float4*)(om + rb0))[1] = make_float4(mv0[4], mv0[5], mv0[6], mv0[7]);
        ((float4*)(om + rb1))[0] = make_float4(mv1[0], mv1[1], mv1[2], mv1[3]);
        ((float4*)(om + rb1))[1] = make_float4(mv1[4], mv1[5], mv1[6], mv1[7]);
        ((float4*)(ol + rb0))[0] = make_float4(lv0[0], lv0[1], lv0[2], lv0[3]);
        ((float4*)(ol + rb0))[1] = make_float4(lv0[4], lv0[5], lv0[6], lv0[7]);
        ((float4*)(ol + rb1))[0] = make_float4(lv1[0], lv1[1], lv1[2], lv1[3]);
        ((float4*)(ol + rb1))[1] = make_float4(lv1[4], lv1[5], lv1[6], lv1[7]);
        ((float4*)(oz + rb0))[0] = make_float4(z0[0], z0[1], z0[2], z0[3]);
        ((float4*)(oz + rb0))[1] = make_float4(z0[4], z0[5], z0[6], z0[7]);
        ((float4*)(oz + rb1))[0] = make_float4(z1[0], z1[1], z1[2], z1[3]);
        ((float4*)(oz + rb1))[1] = make_float4(z1[4], z1[5], z1[6], z1[7]);
    }

    // ------- decoder (input pairs over feature axis, per row) -------
    const int OID[12] = {0,1,2,3,10,11,12,13,14,18,22,26};
    u64 inp0[10], inp1[10];
    #pragma unroll
    for (int p = 0; p < 6; p++) {
        inp0[p] = pack2(initial_c[(size_t)r0 * 30 + OID[2*p]],
                        initial_c[(size_t)r0 * 30 + OID[2*p+1]]);
        inp1[p] = pack2(initial_c[(size_t)r1 * 30 + OID[2*p]],
                        initial_c[(size_t)r1 * 30 + OID[2*p+1]]);
    }
    #pragma unroll
    for (int u = 0; u < 4; u++) {
        inp0[6 + u] = pack2(z0[2*u], z0[2*u+1]);
        inp1[6 + u] = pack2(z1[2*u], z1[2*u+1]);
    }

    u64 oa0[6], oa1[6];
    {
        const ulonglong2* bb = (const ulonglong2*)(s.bd2p);
        #pragma unroll
        for (int q = 0; q < 3; q++) {
            ulonglong2 b = bb[q];
            oa0[2*q] = b.x; oa0[2*q+1] = b.y;
            oa1[2*q] = b.x; oa1[2*q+1] = b.y;
        }
    }
    #pragma unroll 4
    for (int h = 0; h < 32; h++) {
        const ulonglong2* wr = (const ulonglong2*)(s.wd1p + h * 10);
        u64 aA0 = 0ull, aB0 = 0ull, aA1 = 0ull, aB1 = 0ull;
        #pragma unroll
        for (int q = 0; q < 5; q++) {
            ulonglong2 w = wr[q];
            aA0 = fma2(aA0, w.x, inp0[2*q]);
            aB0 = fma2(aB0, w.y, inp0[2*q+1]);
            aA1 = fma2(aA1, w.x, inp1[2*q]);
            aB1 = fma2(aB1, w.y, inp1[2*q+1]);
        }
        float bias = s.bd1s[h];
        float a0s = fmaxf(bias + hadd2(add2(aA0, aB0)), 0.f);
        float a1s = fmaxf(bias + hadd2(add2(aA1, aB1)), 0.f);
        u64 a20 = pack2(a0s, a0s), a21 = pack2(a1s, a1s);
        const ulonglong2* w2r = (const ulonglong2*)(s.wd2p + h * 6);
        #pragma unroll
        for (int q = 0; q < 3; q++) {
            ulonglong2 w = w2r[q];
            oa0[2*q]   = fma2(oa0[2*q],   w.x, a20);
            oa1[2*q]   = fma2(oa1[2*q],   w.x, a21);
            oa0[2*q+1] = fma2(oa0[2*q+1], w.y, a20);
            oa1[2*q+1] = fma2(oa1[2*q+1], w.y, a21);
        }
    }
    {
        float r0v[12], r1v[12];
        #pragma unroll
        for (int q = 0; q < 6; q++) {
            float ax, ay;
            unpack2(oa0[q], ax, ay);
            r0v[2*q]   = 1.f / (1.f + __expf(-ax));
            r0v[2*q+1] = 1.f / (1.f + __expf(-ay));
            unpack2(oa1[q], ax, ay);
            r1v[2*q]   = 1.f / (1.f + __expf(-ax));
            r1v[2*q+1] = 1.f / (1.f + __expf(-ay));
        }
        float4* o0 = (float4*)(out + (size_t)r0 * 12);
        float4* o1 = (float4*)(out + (size_t)r1 * 12);
        o0[0] = make_float4(r0v[0], r0v[1], r0v[2],  r0v[3]);
        o0[1] = make_float4(r0v[4], r0v[5], r0v[6],  r0v[7]);
        o0[2] = make_float4(r0v[8], r0v[9], r0v[10], r0v[11]);
        o1[0] = make_float4(r1v[0], r1v[1], r1v[2],  r1v[3]);
        o1[1] = make_float4(r1v[4], r1v[5], r1v[6],  r1v[7]);
        o1[2] = make_float4(r1v[8], r1v[9], r1v[10], r1v[11]);
    }
}

extern "C" void kernel_launch(void* const* d_in, const int* in_sizes, int n_in,
                              void* d_out, int out_size) {
    const float* initial_c = (const float*)d_in[0];
    // d_in[1] = initial_s : unused by the reference
    const float* current_c = (const float*)d_in[2];
    const float* eps       = (const float*)d_in[3];
    const float* W1  = (const float*)d_in[4];
    const float* b1  = (const float*)d_in[5];
    const float* W2  = (const float*)d_in[6];
    const float* b2  = (const float*)d_in[7];
    const float* W3  = (const float*)d_in[8];
    const float* b3  = (const float*)d_in[9];
    const float* Wm  = (const float*)d_in[10];
    const float* bm  = (const float*)d_in[11];
    const float* Wv  = (const float*)d_in[12];
    const float* bv  = (const float*)d_in[13];
    const float* Wd1 = (const float*)d_in[14];
    const float* bd1 = (const float*)d_in[15];
    const float* Wd2 = (const float*)d_in[16];
    const float* bd2 = (const float*)d_in[17];
    float* out = (float*)d_out;

    const int B = in_sizes[0] / 30;
    const int threads = B / 2;
    const int blocks = (threads + NT - 1) / NT;
    const int smem_bytes = (int)sizeof(Smem);

    cudaFuncSetAttribute(vae_kernel, cudaFuncAttributeMaxDynamicSharedMemorySize, smem_bytes);
    vae_kernel<<<blocks, NT, smem_bytes>>>(
        initial_c, current_c, eps,
        W1, b1, W2, b2, W3, b3, Wm, bm, Wv, bv, Wd1, bd1, Wd2, bd2,
        out, B);
}